// round 1
// baseline (speedup 1.0000x reference)
#include <cuda_runtime.h>
#include <math.h>

#define BB 8192
#define DD 64
#define NT 64          // number of 128-row tiles (8192/128)
#define NTRI 2080      // NT*(NT+1)/2

// Scratch (static device globals; no allocation allowed)
__device__ float g_invvar[2 * DD];
__device__ float g_Xs[2][DD * BB];   // scaled diff, transposed [d][r]
__device__ float g_Xu[2][DD * BB];   // unscaled diff, transposed [d][r]
__device__ float g_partial[2 * BB * NT]; // [pair][row][slot]

// ---------------------------------------------------------------------------
// Kernel 1: per-feature population variance of concat(a,b)+1e-4 -> 1/var
// ---------------------------------------------------------------------------
__global__ void var_kernel(const float* __restrict__ anchor,
                           const float* __restrict__ positive,
                           const float* __restrict__ negative) {
    int pair = blockIdx.x >> 6;   // 0: positive, 1: negative
    int d    = blockIdx.x & 63;
    const float* bptr = pair ? negative : positive;
    float s1 = 0.f, s2 = 0.f;
    for (int r = threadIdx.x; r < BB; r += blockDim.x) {
        float x = anchor[r * DD + d] + 1e-4f;
        float y = bptr[r * DD + d] + 1e-4f;
        s1 += x + y;
        s2 += x * x + y * y;
    }
    __shared__ float sh1[256];
    __shared__ float sh2[256];
    sh1[threadIdx.x] = s1;
    sh2[threadIdx.x] = s2;
    __syncthreads();
    for (int off = 128; off > 0; off >>= 1) {
        if (threadIdx.x < off) {
            sh1[threadIdx.x] += sh1[threadIdx.x + off];
            sh2[threadIdx.x] += sh2[threadIdx.x + off];
        }
        __syncthreads();
    }
    if (threadIdx.x == 0) {
        const float n = 2.0f * BB;
        float mean = sh1[0] / n;
        float var  = sh2[0] / n - mean * mean;
        g_invvar[pair * DD + d] = 1.0f / var;
    }
}

// ---------------------------------------------------------------------------
// Kernel 2: build diff (and scaled diff) TRANSPOSED: X[d][r] = a[r][d]-b[r][d]
// 32x32 smem tile transpose, coalesced both sides.
// ---------------------------------------------------------------------------
__global__ void build_kernel(const float* __restrict__ anchor,
                             const float* __restrict__ positive,
                             const float* __restrict__ negative) {
    int pair = blockIdx.z;
    int d0 = blockIdx.y * 32;
    int r0 = blockIdx.x * 32;
    const float* bptr = pair ? negative : positive;
    __shared__ float tile[32][33];
    int tx = threadIdx.x, ty = threadIdx.y;
#pragma unroll
    for (int s = 0; s < 4; s++) {
        int r = r0 + ty + 8 * s;
        int d = d0 + tx;
        tile[ty + 8 * s][tx] = anchor[r * DD + d] - bptr[r * DD + d];
    }
    __syncthreads();
#pragma unroll
    for (int s = 0; s < 4; s++) {
        int d = d0 + ty + 8 * s;
        int r = r0 + tx;
        float v = tile[tx][ty + 8 * s];
        g_Xu[pair][d * BB + r] = v;
        g_Xs[pair][d * BB + r] = v * g_invvar[pair * DD + d];
    }
}

// ---------------------------------------------------------------------------
// Kernel 3: triangular-tiled 128x128 GEMM (K=64) + fused sqrt + partial sums.
// q symmetric: tile (ti<=tj) emits row-partials (rows of ti, slot tj) and,
// when ti<tj, col-partials (rows of tj, slot ti). Each (row,slot) written once.
// ---------------------------------------------------------------------------
__global__ __launch_bounds__(256) void gemm_kernel() {
    extern __shared__ float smem[];
    float* As = smem;             // [64][128] scaled rows of tile ti
    float* Bs = smem + 64 * 128;  // [64][128] unscaled rows of tile tj

    int pair = blockIdx.y;
    int t = blockIdx.x;
    int tj = (int)((sqrtf(8.0f * (float)t + 1.0f) - 1.0f) * 0.5f);
    while ((tj + 1) * (tj + 2) / 2 <= t) tj++;
    while (tj * (tj + 1) / 2 > t) tj--;
    int ti = t - tj * (tj + 1) / 2;

    int tid = threadIdx.x;
    const float* __restrict__ Xs = g_Xs[pair];
    const float* __restrict__ Xu = g_Xu[pair];

    // Load tiles: global is [d][r] so smem is naturally [k][m]; fully coalesced,
    // conflict-free float4 stores.
    for (int i = tid; i < 64 * 32; i += 256) {
        int k = i >> 5;
        int m4 = (i & 31) << 2;
        *(float4*)&As[k * 128 + m4] = *(const float4*)&Xs[k * BB + ti * 128 + m4];
        *(float4*)&Bs[k * 128 + m4] = *(const float4*)&Xu[k * BB + tj * 128 + m4];
    }
    __syncthreads();

    int tx = tid & 15;   // col group
    int ty = tid >> 4;   // row group
    float acc[8][8];
#pragma unroll
    for (int i = 0; i < 8; i++)
#pragma unroll
        for (int j = 0; j < 8; j++) acc[i][j] = 0.f;

#pragma unroll 8
    for (int k = 0; k < 64; k++) {
        float4 a0 = *(const float4*)&As[k * 128 + ty * 8];
        float4 a1 = *(const float4*)&As[k * 128 + ty * 8 + 4];
        float4 b0 = *(const float4*)&Bs[k * 128 + tx * 8];
        float4 b1 = *(const float4*)&Bs[k * 128 + tx * 8 + 4];
        float av[8] = {a0.x, a0.y, a0.z, a0.w, a1.x, a1.y, a1.z, a1.w};
        float bv[8] = {b0.x, b0.y, b0.z, b0.w, b1.x, b1.y, b1.z, b1.w};
#pragma unroll
        for (int i = 0; i < 8; i++)
#pragma unroll
            for (int j = 0; j < 8; j++) acc[i][j] += av[i] * bv[j];
    }

    // Epilogue: s = (q<0 ? 0 : sqrt(q)); accumulate row & col partials.
    float rsum[8], csum[8];
#pragma unroll
    for (int i = 0; i < 8; i++) { rsum[i] = 0.f; csum[i] = 0.f; }
#pragma unroll
    for (int i = 0; i < 8; i++)
#pragma unroll
        for (int j = 0; j < 8; j++) {
            float q = acc[i][j];
            float sv = (q > 0.f) ? sqrtf(q) : 0.f;
            rsum[i] += sv;
            csum[j] += sv;
        }

    // Row partials: reduce across the 16 tx lanes (a half-warp: offsets 1..8).
#pragma unroll
    for (int off = 8; off > 0; off >>= 1)
#pragma unroll
        for (int i = 0; i < 8; i++)
            rsum[i] += __shfl_xor_sync(0xffffffffu, rsum[i], off);
    if (tx == 0) {
#pragma unroll
        for (int i = 0; i < 8; i++)
            g_partial[(pair * BB + ti * 128 + ty * 8 + i) * NT + tj] = rsum[i];
    }

    // Col partials (off-diagonal tiles only): reduce across ty via smem.
    if (ti != tj) {
        __syncthreads();            // done reading As; reuse as reduction buffer
        float* red = smem;          // [16][128]
#pragma unroll
        for (int j = 0; j < 8; j++) red[ty * 128 + tx * 8 + j] = csum[j];
        __syncthreads();
        if (tid < 128) {
            float v = 0.f;
#pragma unroll
            for (int g = 0; g < 16; g++) v += red[g * 128 + tid];
            g_partial[(pair * BB + tj * 128 + tid) * NT + ti] = v;
        }
    }
}

// ---------------------------------------------------------------------------
// Kernel 4: final reduce over 64 slots per row, add sum of EPS_OUT terms.
// ---------------------------------------------------------------------------
__global__ void reduce_kernel(float* __restrict__ out) {
    int idx = blockIdx.x * blockDim.x + threadIdx.x; // 0..16383
    const float* p = &g_partial[idx * NT];
    float s = 0.f;
#pragma unroll
    for (int j = 0; j < NT; j++) s += p[j];
    out[idx] = s + 8192.0f * 1e-6f;
}

extern "C" void kernel_launch(void* const* d_in, const int* in_sizes, int n_in,
                              void* d_out, int out_size) {
    (void)in_sizes; (void)n_in; (void)out_size;
    const float* anchor   = (const float*)d_in[0];
    const float* positive = (const float*)d_in[1];
    const float* negative = (const float*)d_in[2];
    float* out = (float*)d_out;

    var_kernel<<<128, 256>>>(anchor, positive, negative);
    build_kernel<<<dim3(BB / 32, 2, 2), dim3(32, 8)>>>(anchor, positive, negative);
    cudaFuncSetAttribute(gemm_kernel, cudaFuncAttributeMaxDynamicSharedMemorySize, 65536);
    gemm_kernel<<<dim3(NTRI, 2), 256, 65536>>>();
    reduce_kernel<<<64, 256>>>(out);
}

// round 4
// speedup vs baseline: 6.8509x; 6.8509x over previous
#include <cuda_runtime.h>
#include <cuda_bf16.h>
#include <math.h>
#include <stdint.h>

#define BB 8192
#define DD 64
#define NT 64          // 128-row tiles
#define NTRI 2080      // NT*(NT+1)/2

// ---------------- scratch (no allocations allowed) ----------------
__device__ float g_rstd[2][DD];
__device__ __nv_bfloat16 g_Y[2][BB * DD];   // Y[r][d] = (a-b)*rsqrt(var), K-major
__device__ float g_part[2 * BB * NT];       // [pair*B + row][tile-slot]

// ---------------- helpers ----------------
__device__ __forceinline__ uint32_t smem_u32(const void* p) {
    uint32_t a;
    asm("{ .reg .u64 t; cvta.to.shared.u64 t, %1; cvt.u32.u64 %0, t; }" : "=r"(a) : "l"(p));
    return a;
}

__device__ __forceinline__ void ldsm_x4(uint32_t* r, uint32_t addr) {
    asm volatile("ldmatrix.sync.aligned.m8n8.x4.shared.b16 {%0,%1,%2,%3}, [%4];"
                 : "=r"(r[0]), "=r"(r[1]), "=r"(r[2]), "=r"(r[3]) : "r"(addr));
}

__device__ __forceinline__ void mma16816(float* d, const uint32_t* a, const uint32_t* b) {
    asm volatile(
        "mma.sync.aligned.m16n8k16.row.col.f32.bf16.bf16.f32 "
        "{%0,%1,%2,%3}, {%4,%5,%6,%7}, {%8,%9}, {%0,%1,%2,%3};"
        : "+f"(d[0]), "+f"(d[1]), "+f"(d[2]), "+f"(d[3])
        : "r"(a[0]), "r"(a[1]), "r"(a[2]), "r"(a[3]), "r"(b[0]), "r"(b[1]));
}

__device__ __forceinline__ float msqrt(float q) {
    float sv;
    asm("sqrt.approx.f32 %0, %1;" : "=f"(sv) : "f"(q));
    return q > 0.f ? sv : 0.f;
}

// ---------------------------------------------------------------------------
// Kernel 1: per-feature population variance of concat(a,b)+1e-4 -> rsqrt(var)
// ---------------------------------------------------------------------------
__global__ void var_kernel(const float* __restrict__ anchor,
                           const float* __restrict__ positive,
                           const float* __restrict__ negative) {
    int pair = blockIdx.x >> 6;
    int d    = blockIdx.x & 63;
    const float* bptr = pair ? negative : positive;
    float s1 = 0.f, s2 = 0.f;
    for (int r = threadIdx.x; r < BB; r += blockDim.x) {
        float x = anchor[r * DD + d] + 1e-4f;
        float y = bptr[r * DD + d] + 1e-4f;
        s1 += x + y;
        s2 += x * x + y * y;
    }
    __shared__ float sh1[256];
    __shared__ float sh2[256];
    sh1[threadIdx.x] = s1;
    sh2[threadIdx.x] = s2;
    __syncthreads();
    for (int off = 128; off > 0; off >>= 1) {
        if (threadIdx.x < off) {
            sh1[threadIdx.x] += sh1[threadIdx.x + off];
            sh2[threadIdx.x] += sh2[threadIdx.x + off];
        }
        __syncthreads();
    }
    if (threadIdx.x == 0) {
        const float n = 2.0f * BB;
        float mean = sh1[0] / n;
        float var  = sh2[0] / n - mean * mean;
        g_rstd[pair][d] = 1.0f / sqrtf(var);
    }
}

// ---------------------------------------------------------------------------
// Kernel 2: Y[pair][r][d] = (a[r][d]-b[r][d]) * rstd[d]  (bf16, K-major rows)
// ---------------------------------------------------------------------------
__global__ void build_kernel(const float* __restrict__ anchor,
                             const float* __restrict__ positive,
                             const float* __restrict__ negative) {
    int idx = blockIdx.x * blockDim.x + threadIdx.x;  // 0 .. 2*8192*16-1
    int pair = idx >> 17;
    int rem  = idx & 131071;
    int r = rem >> 4;
    int g = rem & 15;
    const float* bp = pair ? negative : positive;
    float4 av = reinterpret_cast<const float4*>(anchor)[r * 16 + g];
    float4 bv = reinterpret_cast<const float4*>(bp)[r * 16 + g];
    float4 rs = reinterpret_cast<const float4*>(g_rstd[pair])[g];
    __nv_bfloat162 lo = __floats2bfloat162_rn((av.x - bv.x) * rs.x, (av.y - bv.y) * rs.y);
    __nv_bfloat162 hi = __floats2bfloat162_rn((av.z - bv.z) * rs.z, (av.w - bv.w) * rs.w);
    uint2 pk;
    *reinterpret_cast<__nv_bfloat162*>(&pk.x) = lo;
    *reinterpret_cast<__nv_bfloat162*>(&pk.y) = hi;
    *reinterpret_cast<uint2*>(&g_Y[pair][r * DD + g * 4]) = pk;
}

// ---------------------------------------------------------------------------
// Kernel 3: triangular 128x128 tile, mma.sync bf16 (4 warps, 64x64 warp tile),
// fused sqrt + row/col partial sums. Accumulators register-resident.
// Smem tile: [row][64 bf16] rows of 128B with SW128 xor swizzle
//   (swizzled off = row*128 + (kb ^ ((row&7)*16)))
// ---------------------------------------------------------------------------
#define SMEM_A 0
#define SMEM_B 16384
#define SMEM_TOTAL 32768

__global__ __launch_bounds__(128, 1) void gemm_kernel() {
    extern __shared__ char smem[];
    uint32_t smem_base = smem_u32(smem);
    int tid = threadIdx.x;
    int lane = tid & 31;
    int wid = tid >> 5;
    int wr = wid >> 1;    // warp row (0,1) -> rows wr*64
    int wc = wid & 1;     // warp col (0,1) -> cols wc*64

    int pair = blockIdx.y;
    int t = blockIdx.x;
    int tj = (int)((sqrtf(8.0f * (float)t + 1.0f) - 1.0f) * 0.5f);
    while ((tj + 1) * (tj + 2) / 2 <= t) tj++;
    while (tj * (tj + 1) / 2 > t) tj--;
    int ti = t - tj * (tj + 1) / 2;

    // ---- load tiles (rows = 128B, swizzled 16B units) ----
    const uint4* gA = reinterpret_cast<const uint4*>(g_Y[pair] + ti * 128 * DD);
    const uint4* gB = reinterpret_cast<const uint4*>(g_Y[pair] + tj * 128 * DD);
#pragma unroll
    for (int i = 0; i < 8; i++) {
        int c = i * 128 + tid;                  // uint4 index: row*8 + group
        uint32_t off = (uint32_t)c * 16;
        uint32_t sw = off ^ ((off >> 3) & 0x70);
        *reinterpret_cast<uint4*>(smem + SMEM_A + sw) = gA[c];
        *reinterpret_cast<uint4*>(smem + SMEM_B + sw) = gB[c];
    }
    __syncthreads();

    // ---- mainloop: 4 k16 steps, warp tile 64x64 = 4 mtiles x 8 ntiles ----
    float acc[4][8][4];
#pragma unroll
    for (int mt = 0; mt < 4; mt++)
#pragma unroll
        for (int nt = 0; nt < 8; nt++)
#pragma unroll
            for (int f = 0; f < 4; f++) acc[mt][nt][f] = 0.f;

    int a_row = lane & 15;                       // + wr*64 + mt*16
    int a_kb  = (lane >> 4) * 16;                // + kk*32
    int b_row = (lane & 7) + ((lane >> 4) << 3); // + wc*64 + ng*16
    int b_kb  = ((lane >> 3) & 1) * 16;          // + kk*32

#pragma unroll
    for (int kk = 0; kk < 4; kk++) {
        uint32_t af[4][4];
#pragma unroll
        for (int mt = 0; mt < 4; mt++) {
            int row = wr * 64 + mt * 16 + a_row;
            int kb = kk * 32 + a_kb;
            uint32_t addr = smem_base + SMEM_A + row * 128 + (kb ^ ((row & 7) * 16));
            ldsm_x4(af[mt], addr);
        }
        uint32_t bf[4][4];
#pragma unroll
        for (int ng = 0; ng < 4; ng++) {
            int row = wc * 64 + ng * 16 + b_row;
            int kb = kk * 32 + b_kb;
            uint32_t addr = smem_base + SMEM_B + row * 128 + (kb ^ ((row & 7) * 16));
            ldsm_x4(bf[ng], addr);
        }
#pragma unroll
        for (int mt = 0; mt < 4; mt++)
#pragma unroll
            for (int nt = 0; nt < 8; nt++)
                mma16816(acc[mt][nt], af[mt], &bf[nt >> 1][(nt & 1) * 2]);
    }

    // ---- fused epilogue: sqrt + row/col partials ----
    // acc[mt][nt]: c0=(r=lane/4, c=(lane%4)*2) c1=c+1 c2=(r+8,c) c3=(r+8,c+1)
    float rs[4][2], cs[8][2];
#pragma unroll
    for (int mt = 0; mt < 4; mt++) { rs[mt][0] = 0.f; rs[mt][1] = 0.f; }
#pragma unroll
    for (int nt = 0; nt < 8; nt++) { cs[nt][0] = 0.f; cs[nt][1] = 0.f; }
#pragma unroll
    for (int mt = 0; mt < 4; mt++)
#pragma unroll
        for (int nt = 0; nt < 8; nt++) {
            float s0 = msqrt(acc[mt][nt][0]);
            float s1 = msqrt(acc[mt][nt][1]);
            float s2 = msqrt(acc[mt][nt][2]);
            float s3 = msqrt(acc[mt][nt][3]);
            rs[mt][0] += s0 + s1;
            rs[mt][1] += s2 + s3;
            cs[nt][0] += s0 + s2;
            cs[nt][1] += s1 + s3;
        }

    // row partials: reduce across the 4 lanes sharing a row (lane%4)
#pragma unroll
    for (int o = 1; o <= 2; o <<= 1)
#pragma unroll
        for (int mt = 0; mt < 4; mt++) {
            rs[mt][0] += __shfl_xor_sync(0xffffffffu, rs[mt][0], o);
            rs[mt][1] += __shfl_xor_sync(0xffffffffu, rs[mt][1], o);
        }
    // col partials: reduce across the 8 lanes sharing a col (lane/4)
#pragma unroll
    for (int o = 4; o <= 16; o <<= 1)
#pragma unroll
        for (int nt = 0; nt < 8; nt++) {
            cs[nt][0] += __shfl_xor_sync(0xffffffffu, cs[nt][0], o);
            cs[nt][1] += __shfl_xor_sync(0xffffffffu, cs[nt][1], o);
        }

    __syncthreads();   // smem tile reads done; reuse as reduction buffers
    float* srow = reinterpret_cast<float*>(smem);        // [128][2]
    float* scol = srow + 256;                            // [128][2]

    if ((lane & 3) == 0) {
        int g = lane >> 2;  // 0..7
#pragma unroll
        for (int mt = 0; mt < 4; mt++) {
            srow[(wr * 64 + mt * 16 + g) * 2 + wc]     = rs[mt][0];
            srow[(wr * 64 + mt * 16 + g + 8) * 2 + wc] = rs[mt][1];
        }
    }
    if (lane < 4) {
#pragma unroll
        for (int nt = 0; nt < 8; nt++) {
            scol[(wc * 64 + nt * 8 + lane * 2) * 2 + wr]     = cs[nt][0];
            scol[(wc * 64 + nt * 8 + lane * 2 + 1) * 2 + wr] = cs[nt][1];
        }
    }
    __syncthreads();

    float rrow = srow[tid * 2] + srow[tid * 2 + 1];
    g_part[(pair * BB + ti * 128 + tid) * NT + tj] = rrow;
    if (ti != tj) {
        float rcol = scol[tid * 2] + scol[tid * 2 + 1];
        g_part[(pair * BB + tj * 128 + tid) * NT + ti] = rcol;
    }
}

// ---------------------------------------------------------------------------
// Kernel 4: reduce 64 slots per row + EPS_OUT * B
// ---------------------------------------------------------------------------
__global__ void reduce_kernel(float* __restrict__ out) {
    int idx = blockIdx.x * blockDim.x + threadIdx.x;  // 0..16383
    const float4* p = reinterpret_cast<const float4*>(&g_part[idx * NT]);
    float s = 0.f;
#pragma unroll
    for (int j = 0; j < 16; j++) {
        float4 v = p[j];
        s += (v.x + v.y) + (v.z + v.w);
    }
    out[idx] = s + 8192.0f * 1e-6f;
}

extern "C" void kernel_launch(void* const* d_in, const int* in_sizes, int n_in,
                              void* d_out, int out_size) {
    (void)in_sizes; (void)n_in; (void)out_size;
    const float* anchor   = (const float*)d_in[0];
    const float* positive = (const float*)d_in[1];
    const float* negative = (const float*)d_in[2];
    float* out = (float*)d_out;

    var_kernel<<<128, 256>>>(anchor, positive, negative);
    build_kernel<<<1024, 256>>>(anchor, positive, negative);
    cudaFuncSetAttribute(gemm_kernel, cudaFuncAttributeMaxDynamicSharedMemorySize, SMEM_TOTAL);
    gemm_kernel<<<dim3(NTRI, 2), 128, SMEM_TOTAL>>>();
    reduce_kernel<<<128, 128>>>(out);
}

// round 5
// speedup vs baseline: 7.1837x; 1.0486x over previous
#include <cuda_runtime.h>
#include <cuda_bf16.h>
#include <math.h>
#include <stdint.h>

#define BB 8192
#define DD 64
#define NT 64          // 128-row tiles
#define NTRI 2080      // NT*(NT+1)/2

// ---------------- scratch (no allocations allowed) ----------------
__device__ float g_rstd[2][DD];
__device__ float g_vpart[2 * 2 * 64 * 64];  // [pair][s1|s2][chunk][d]
__device__ __nv_bfloat16 g_Y[2][BB * DD];   // Y[r][d] = (a-b)*rsqrt(var), K-major
__device__ float g_part[2 * BB * NT];       // [pair*B + row][tile-slot]

// ---------------- helpers ----------------
__device__ __forceinline__ uint32_t smem_u32(const void* p) {
    uint32_t a;
    asm("{ .reg .u64 t; cvta.to.shared.u64 t, %1; cvt.u32.u64 %0, t; }" : "=r"(a) : "l"(p));
    return a;
}

__device__ __forceinline__ void ldsm_x4(uint32_t* r, uint32_t addr) {
    asm volatile("ldmatrix.sync.aligned.m8n8.x4.shared.b16 {%0,%1,%2,%3}, [%4];"
                 : "=r"(r[0]), "=r"(r[1]), "=r"(r[2]), "=r"(r[3]) : "r"(addr));
}

__device__ __forceinline__ void mma16816(float* d, const uint32_t* a, const uint32_t* b) {
    asm volatile(
        "mma.sync.aligned.m16n8k16.row.col.f32.bf16.bf16.f32 "
        "{%0,%1,%2,%3}, {%4,%5,%6,%7}, {%8,%9}, {%0,%1,%2,%3};"
        : "+f"(d[0]), "+f"(d[1]), "+f"(d[2]), "+f"(d[3])
        : "r"(a[0]), "r"(a[1]), "r"(a[2]), "r"(a[3]), "r"(b[0]), "r"(b[1]));
}

__device__ __forceinline__ float msqrt(float q) {
    float sv;
    asm("sqrt.approx.f32 %0, %1;" : "=f"(sv) : "f"(q));
    return q > 0.f ? sv : 0.f;
}

// ---------------------------------------------------------------------------
// Kernel 1a: coalesced per-block partial sums (s1, s2) per feature.
// Block = (pair, 128-row chunk). Thread t: feature-group g = t&15 (float4),
// rows rr = t>>4 (+16 per pass). Fully coalesced float4 reads.
// ---------------------------------------------------------------------------
__global__ __launch_bounds__(256) void varA_kernel(const float* __restrict__ anchor,
                                                   const float* __restrict__ positive,
                                                   const float* __restrict__ negative) {
    int pair  = blockIdx.x >> 6;
    int chunk = blockIdx.x & 63;
    const float* bp = pair ? negative : positive;
    int t = threadIdx.x;
    int g = t & 15;
    int rr = t >> 4;

    float s1[4] = {0.f, 0.f, 0.f, 0.f};
    float s2[4] = {0.f, 0.f, 0.f, 0.f};
#pragma unroll
    for (int p = 0; p < 8; p++) {
        int r = chunk * 128 + p * 16 + rr;
        float4 a = reinterpret_cast<const float4*>(anchor)[r * 16 + g];
        float4 b = reinterpret_cast<const float4*>(bp)[r * 16 + g];
        float x, y;
        x = a.x + 1e-4f; y = b.x + 1e-4f; s1[0] += x + y; s2[0] += x * x + y * y;
        x = a.y + 1e-4f; y = b.y + 1e-4f; s1[1] += x + y; s2[1] += x * x + y * y;
        x = a.z + 1e-4f; y = b.z + 1e-4f; s1[2] += x + y; s2[2] += x * x + y * y;
        x = a.w + 1e-4f; y = b.w + 1e-4f; s1[3] += x + y; s2[3] += x * x + y * y;
    }
    __shared__ float sh[256 * 8];
#pragma unroll
    for (int c = 0; c < 4; c++) {
        sh[t * 8 + c]     = s1[c];
        sh[t * 8 + 4 + c] = s2[c];
    }
    __syncthreads();
    if (t < 128) {
        int d  = t & 63;
        int wh = t >> 6;        // 0: s1, 1: s2
        int gg = d >> 2, c = d & 3;
        float s = 0.f;
#pragma unroll
        for (int k = 0; k < 16; k++)
            s += sh[(gg + 16 * k) * 8 + wh * 4 + c];
        g_vpart[((pair * 2 + wh) * 64 + chunk) * 64 + d] = s;
    }
}

// ---------------------------------------------------------------------------
// Kernel 1b: finish variance -> rstd (128 threads, one block)
// ---------------------------------------------------------------------------
__global__ void varB_kernel() {
    int t = threadIdx.x;        // 0..127
    int pair = t >> 6, d = t & 63;
    float s1 = 0.f, s2 = 0.f;
#pragma unroll 8
    for (int chunk = 0; chunk < 64; chunk++) {
        s1 += g_vpart[((pair * 2 + 0) * 64 + chunk) * 64 + d];
        s2 += g_vpart[((pair * 2 + 1) * 64 + chunk) * 64 + d];
    }
    const float n = 2.0f * BB;
    float mean = s1 / n;
    float var  = s2 / n - mean * mean;
    g_rstd[pair][d] = 1.0f / sqrtf(var);
}

// ---------------------------------------------------------------------------
// Kernel 2: Y[pair][r][d] = (a[r][d]-b[r][d]) * rstd[d]  (bf16, K-major rows)
// ---------------------------------------------------------------------------
__global__ void build_kernel(const float* __restrict__ anchor,
                             const float* __restrict__ positive,
                             const float* __restrict__ negative) {
    int idx = blockIdx.x * blockDim.x + threadIdx.x;  // 0 .. 2*8192*16-1
    int pair = idx >> 17;
    int rem  = idx & 131071;
    int r = rem >> 4;
    int g = rem & 15;
    const float* bp = pair ? negative : positive;
    float4 av = reinterpret_cast<const float4*>(anchor)[r * 16 + g];
    float4 bv = reinterpret_cast<const float4*>(bp)[r * 16 + g];
    float4 rs = reinterpret_cast<const float4*>(g_rstd[pair])[g];
    __nv_bfloat162 lo = __floats2bfloat162_rn((av.x - bv.x) * rs.x, (av.y - bv.y) * rs.y);
    __nv_bfloat162 hi = __floats2bfloat162_rn((av.z - bv.z) * rs.z, (av.w - bv.w) * rs.w);
    uint2 pk;
    *reinterpret_cast<__nv_bfloat162*>(&pk.x) = lo;
    *reinterpret_cast<__nv_bfloat162*>(&pk.y) = hi;
    *reinterpret_cast<uint2*>(&g_Y[pair][r * DD + g * 4]) = pk;
}

// ---------------------------------------------------------------------------
// Kernel 3: triangular 128x128 tile, mma.sync bf16 (4 warps, 64x64 warp tile),
// fused sqrt + row/col partial sums. 2 CTAs/SM for phase overlap.
// ---------------------------------------------------------------------------
#define SMEM_A 0
#define SMEM_B 16384
#define SMEM_TOTAL 32768

__global__ __launch_bounds__(128, 2) void gemm_kernel() {
    extern __shared__ char smem[];
    uint32_t smem_base = smem_u32(smem);
    int tid = threadIdx.x;
    int lane = tid & 31;
    int wid = tid >> 5;
    int wr = wid >> 1;    // warp row (0,1) -> rows wr*64
    int wc = wid & 1;     // warp col (0,1) -> cols wc*64

    int pair = blockIdx.y;
    int t = blockIdx.x;
    int tj = (int)((sqrtf(8.0f * (float)t + 1.0f) - 1.0f) * 0.5f);
    while ((tj + 1) * (tj + 2) / 2 <= t) tj++;
    while (tj * (tj + 1) / 2 > t) tj--;
    int ti = t - tj * (tj + 1) / 2;

    // ---- load tiles (rows = 128B, swizzled 16B units) ----
    const uint4* gA = reinterpret_cast<const uint4*>(g_Y[pair] + ti * 128 * DD);
    const uint4* gB = reinterpret_cast<const uint4*>(g_Y[pair] + tj * 128 * DD);
#pragma unroll
    for (int i = 0; i < 8; i++) {
        int c = i * 128 + tid;                  // uint4 index: row*8 + group
        uint32_t off = (uint32_t)c * 16;
        uint32_t sw = off ^ ((off >> 3) & 0x70);
        *reinterpret_cast<uint4*>(smem + SMEM_A + sw) = gA[c];
        *reinterpret_cast<uint4*>(smem + SMEM_B + sw) = gB[c];
    }
    __syncthreads();

    // ---- mainloop: 4 k16 steps, warp tile 64x64 = 4 mtiles x 8 ntiles ----
    float acc[4][8][4];
#pragma unroll
    for (int mt = 0; mt < 4; mt++)
#pragma unroll
        for (int nt = 0; nt < 8; nt++)
#pragma unroll
            for (int f = 0; f < 4; f++) acc[mt][nt][f] = 0.f;

    int a_row = lane & 15;                       // + wr*64 + mt*16
    int a_kb  = (lane >> 4) * 16;                // + kk*32
    int b_row = (lane & 7) + ((lane >> 4) << 3); // + wc*64 + ng*16
    int b_kb  = ((lane >> 3) & 1) * 16;          // + kk*32

#pragma unroll
    for (int kk = 0; kk < 4; kk++) {
        uint32_t af[4][4];
#pragma unroll
        for (int mt = 0; mt < 4; mt++) {
            int row = wr * 64 + mt * 16 + a_row;
            int kb = kk * 32 + a_kb;
            uint32_t addr = smem_base + SMEM_A + row * 128 + (kb ^ ((row & 7) * 16));
            ldsm_x4(af[mt], addr);
        }
        uint32_t bf[4][4];
#pragma unroll
        for (int ng = 0; ng < 4; ng++) {
            int row = wc * 64 + ng * 16 + b_row;
            int kb = kk * 32 + b_kb;
            uint32_t addr = smem_base + SMEM_B + row * 128 + (kb ^ ((row & 7) * 16));
            ldsm_x4(bf[ng], addr);
        }
#pragma unroll
        for (int mt = 0; mt < 4; mt++)
#pragma unroll
            for (int nt = 0; nt < 8; nt++)
                mma16816(acc[mt][nt], af[mt], &bf[nt >> 1][(nt & 1) * 2]);
    }

    // ---- fused epilogue: sqrt + row/col partials ----
    float rs[4][2], cs[8][2];
#pragma unroll
    for (int mt = 0; mt < 4; mt++) { rs[mt][0] = 0.f; rs[mt][1] = 0.f; }
#pragma unroll
    for (int nt = 0; nt < 8; nt++) { cs[nt][0] = 0.f; cs[nt][1] = 0.f; }
#pragma unroll
    for (int mt = 0; mt < 4; mt++)
#pragma unroll
        for (int nt = 0; nt < 8; nt++) {
            float s0 = msqrt(acc[mt][nt][0]);
            float s1 = msqrt(acc[mt][nt][1]);
            float s2 = msqrt(acc[mt][nt][2]);
            float s3 = msqrt(acc[mt][nt][3]);
            rs[mt][0] += s0 + s1;
            rs[mt][1] += s2 + s3;
            cs[nt][0] += s0 + s2;
            cs[nt][1] += s1 + s3;
        }

    // row partials: reduce across the 4 lanes sharing a row (lane%4)
#pragma unroll
    for (int o = 1; o <= 2; o <<= 1)
#pragma unroll
        for (int mt = 0; mt < 4; mt++) {
            rs[mt][0] += __shfl_xor_sync(0xffffffffu, rs[mt][0], o);
            rs[mt][1] += __shfl_xor_sync(0xffffffffu, rs[mt][1], o);
        }
    // col partials: reduce across the 8 lanes sharing a col (lane/4)
#pragma unroll
    for (int o = 4; o <= 16; o <<= 1)
#pragma unroll
        for (int nt = 0; nt < 8; nt++) {
            cs[nt][0] += __shfl_xor_sync(0xffffffffu, cs[nt][0], o);
            cs[nt][1] += __shfl_xor_sync(0xffffffffu, cs[nt][1], o);
        }

    __syncthreads();   // smem tile reads done; reuse as reduction buffers
    float* srow = reinterpret_cast<float*>(smem);        // [128][2]
    float* scol = srow + 256;                            // [128][2]

    if ((lane & 3) == 0) {
        int g = lane >> 2;  // 0..7
#pragma unroll
        for (int mt = 0; mt < 4; mt++) {
            srow[(wr * 64 + mt * 16 + g) * 2 + wc]     = rs[mt][0];
            srow[(wr * 64 + mt * 16 + g + 8) * 2 + wc] = rs[mt][1];
        }
    }
    if (lane < 4) {
#pragma unroll
        for (int nt = 0; nt < 8; nt++) {
            scol[(wc * 64 + nt * 8 + lane * 2) * 2 + wr]     = cs[nt][0];
            scol[(wc * 64 + nt * 8 + lane * 2 + 1) * 2 + wr] = cs[nt][1];
        }
    }
    __syncthreads();

    float rrow = srow[tid * 2] + srow[tid * 2 + 1];
    g_part[(pair * BB + ti * 128 + tid) * NT + tj] = rrow;
    if (ti != tj) {
        float rcol = scol[tid * 2] + scol[tid * 2 + 1];
        g_part[(pair * BB + tj * 128 + tid) * NT + ti] = rcol;
    }
}

// ---------------------------------------------------------------------------
// Kernel 4: reduce 64 slots per row, 2 threads per row + shuffle combine
// ---------------------------------------------------------------------------
__global__ void reduce_kernel(float* __restrict__ out) {
    int idx = blockIdx.x * blockDim.x + threadIdx.x;  // 0..32767
    int row = idx >> 1, half = idx & 1;
    const float4* p = reinterpret_cast<const float4*>(&g_part[row * NT + half * 32]);
    float s = 0.f;
#pragma unroll
    for (int j = 0; j < 8; j++) {
        float4 v = p[j];
        s += (v.x + v.y) + (v.z + v.w);
    }
    s += __shfl_xor_sync(0xffffffffu, s, 1);
    if (half == 0) out[row] = s + 8192.0f * 1e-6f;
}

extern "C" void kernel_launch(void* const* d_in, const int* in_sizes, int n_in,
                              void* d_out, int out_size) {
    (void)in_sizes; (void)n_in; (void)out_size;
    const float* anchor   = (const float*)d_in[0];
    const float* positive = (const float*)d_in[1];
    const float* negative = (const float*)d_in[2];
    float* out = (float*)d_out;

    varA_kernel<<<128, 256>>>(anchor, positive, negative);
    varB_kernel<<<1, 128>>>();
    build_kernel<<<1024, 256>>>(anchor, positive, negative);
    cudaFuncSetAttribute(gemm_kernel, cudaFuncAttributeMaxDynamicSharedMemorySize, SMEM_TOTAL);
    gemm_kernel<<<dim3(NTRI, 2), 128, SMEM_TOTAL>>>();
    reduce_kernel<<<256, 128>>>(out);
}

// round 6
// speedup vs baseline: 7.2395x; 1.0078x over previous
#include <cuda_runtime.h>
#include <cuda_bf16.h>
#include <math.h>
#include <stdint.h>

#define BB 8192
#define DD 64
#define NT 64          // 128-row tiles
#define NTRI 2080      // NT*(NT+1)/2

// ---------------- scratch (no allocations allowed) ----------------
__device__ float g_rstd[2][DD];
__device__ float g_vpart[2 * 2 * 64 * 64];  // [pair][s1|s2][chunk][d]
__device__ __nv_bfloat16 g_Y[2][BB * DD];   // Y[r][d] = (a-b)*rsqrt(var), K-major
__device__ float g_part[2 * BB * NT];       // [pair*B + row][tile-slot]

// ---------------- helpers ----------------
__device__ __forceinline__ uint32_t smem_u32(const void* p) {
    uint32_t a;
    asm("{ .reg .u64 t; cvta.to.shared.u64 t, %1; cvt.u32.u64 %0, t; }" : "=r"(a) : "l"(p));
    return a;
}

__device__ __forceinline__ void ldsm_x4(uint32_t* r, uint32_t addr) {
    asm volatile("ldmatrix.sync.aligned.m8n8.x4.shared.b16 {%0,%1,%2,%3}, [%4];"
                 : "=r"(r[0]), "=r"(r[1]), "=r"(r[2]), "=r"(r[3]) : "r"(addr));
}

__device__ __forceinline__ void mma16816(float* d, const uint32_t* a, const uint32_t* b) {
    asm volatile(
        "mma.sync.aligned.m16n8k16.row.col.f32.bf16.bf16.f32 "
        "{%0,%1,%2,%3}, {%4,%5,%6,%7}, {%8,%9}, {%0,%1,%2,%3};"
        : "+f"(d[0]), "+f"(d[1]), "+f"(d[2]), "+f"(d[3])
        : "r"(a[0]), "r"(a[1]), "r"(a[2]), "r"(a[3]), "r"(b[0]), "r"(b[1]));
}

__device__ __forceinline__ float msqrt(float q) {
    float sv;
    asm("sqrt.approx.f32 %0, %1;" : "=f"(sv) : "f"(q));
    return q > 0.f ? sv : 0.f;
}

// ---------------------------------------------------------------------------
// Kernel 1a: coalesced per-block partial sums (s1, s2) per feature.
// ---------------------------------------------------------------------------
__global__ __launch_bounds__(256) void varA_kernel(const float* __restrict__ anchor,
                                                   const float* __restrict__ positive,
                                                   const float* __restrict__ negative) {
    int pair  = blockIdx.x >> 6;
    int chunk = blockIdx.x & 63;
    const float* bp = pair ? negative : positive;
    int t = threadIdx.x;
    int g = t & 15;
    int rr = t >> 4;

    float s1[4] = {0.f, 0.f, 0.f, 0.f};
    float s2[4] = {0.f, 0.f, 0.f, 0.f};
#pragma unroll
    for (int p = 0; p < 8; p++) {
        int r = chunk * 128 + p * 16 + rr;
        float4 a = reinterpret_cast<const float4*>(anchor)[r * 16 + g];
        float4 b = reinterpret_cast<const float4*>(bp)[r * 16 + g];
        float x, y;
        x = a.x + 1e-4f; y = b.x + 1e-4f; s1[0] += x + y; s2[0] += x * x + y * y;
        x = a.y + 1e-4f; y = b.y + 1e-4f; s1[1] += x + y; s2[1] += x * x + y * y;
        x = a.z + 1e-4f; y = b.z + 1e-4f; s1[2] += x + y; s2[2] += x * x + y * y;
        x = a.w + 1e-4f; y = b.w + 1e-4f; s1[3] += x + y; s2[3] += x * x + y * y;
    }
    __shared__ float sh[256 * 8];
#pragma unroll
    for (int c = 0; c < 4; c++) {
        sh[t * 8 + c]     = s1[c];
        sh[t * 8 + 4 + c] = s2[c];
    }
    __syncthreads();
    if (t < 128) {
        int d  = t & 63;
        int wh = t >> 6;        // 0: s1, 1: s2
        int gg = d >> 2, c = d & 3;
        float s = 0.f;
#pragma unroll
        for (int k = 0; k < 16; k++)
            s += sh[(gg + 16 * k) * 8 + wh * 4 + c];
        g_vpart[((pair * 2 + wh) * 64 + chunk) * 64 + d] = s;
    }
}

// ---------------------------------------------------------------------------
// Kernel 1b: finish variance -> rstd (128 threads, one block)
// ---------------------------------------------------------------------------
__global__ void varB_kernel() {
    int t = threadIdx.x;        // 0..127
    int pair = t >> 6, d = t & 63;
    float s1 = 0.f, s2 = 0.f;
#pragma unroll 8
    for (int chunk = 0; chunk < 64; chunk++) {
        s1 += g_vpart[((pair * 2 + 0) * 64 + chunk) * 64 + d];
        s2 += g_vpart[((pair * 2 + 1) * 64 + chunk) * 64 + d];
    }
    const float n = 2.0f * BB;
    float mean = s1 / n;
    float var  = s2 / n - mean * mean;
    g_rstd[pair][d] = 1.0f / sqrtf(var);
}

// ---------------------------------------------------------------------------
// Kernel 2: Y[pair][r][d] = (a[r][d]-b[r][d]) * rstd[d]  (bf16, K-major rows)
// ---------------------------------------------------------------------------
__global__ void build_kernel(const float* __restrict__ anchor,
                             const float* __restrict__ positive,
                             const float* __restrict__ negative) {
    int idx = blockIdx.x * blockDim.x + threadIdx.x;  // 0 .. 2*8192*16-1
    int pair = idx >> 17;
    int rem  = idx & 131071;
    int r = rem >> 4;
    int g = rem & 15;
    const float* bp = pair ? negative : positive;
    float4 av = reinterpret_cast<const float4*>(anchor)[r * 16 + g];
    float4 bv = reinterpret_cast<const float4*>(bp)[r * 16 + g];
    float4 rs = reinterpret_cast<const float4*>(g_rstd[pair])[g];
    __nv_bfloat162 lo = __floats2bfloat162_rn((av.x - bv.x) * rs.x, (av.y - bv.y) * rs.y);
    __nv_bfloat162 hi = __floats2bfloat162_rn((av.z - bv.z) * rs.z, (av.w - bv.w) * rs.w);
    uint2 pk;
    *reinterpret_cast<__nv_bfloat162*>(&pk.x) = lo;
    *reinterpret_cast<__nv_bfloat162*>(&pk.y) = hi;
    *reinterpret_cast<uint2*>(&g_Y[pair][r * DD + g * 4]) = pk;
}

// ---------------------------------------------------------------------------
// Kernel 3: triangular 128x128 tile, 256 threads, 8 warps, warp tile 64x32
// (warp grid 2 rows x 4 cols). Fused sqrt + row/col partial sums.
// acc = 64 regs/thread -> fits 2 CTAs/SM (16 warps) for latency hiding.
// ---------------------------------------------------------------------------
#define SMEM_A 0
#define SMEM_B 16384
#define SMEM_TOTAL 32768

__global__ __launch_bounds__(256, 2) void gemm_kernel() {
    extern __shared__ char smem[];
    uint32_t smem_base = smem_u32(smem);
    int tid = threadIdx.x;
    int lane = tid & 31;
    int wid = tid >> 5;
    int wr = wid >> 2;    // warp row (0,1) -> rows wr*64
    int wc = wid & 3;     // warp col (0..3) -> cols wc*32

    int pair = blockIdx.y;
    int t = blockIdx.x;
    int tj = (int)((sqrtf(8.0f * (float)t + 1.0f) - 1.0f) * 0.5f);
    while ((tj + 1) * (tj + 2) / 2 <= t) tj++;
    while (tj * (tj + 1) / 2 > t) tj--;
    int ti = t - tj * (tj + 1) / 2;

    // ---- load tiles (rows = 128B, swizzled 16B units) ----
    const uint4* gA = reinterpret_cast<const uint4*>(g_Y[pair] + ti * 128 * DD);
    const uint4* gB = reinterpret_cast<const uint4*>(g_Y[pair] + tj * 128 * DD);
#pragma unroll
    for (int i = 0; i < 4; i++) {
        int c = i * 256 + tid;                  // uint4 index: row*8 + group
        uint32_t off = (uint32_t)c * 16;
        uint32_t sw = off ^ ((off >> 3) & 0x70);
        *reinterpret_cast<uint4*>(smem + SMEM_A + sw) = gA[c];
        *reinterpret_cast<uint4*>(smem + SMEM_B + sw) = gB[c];
    }
    __syncthreads();

    // ---- mainloop: 4 k16 steps, warp tile 64x32 = 4 mtiles x 4 ntiles ----
    float acc[4][4][4];
#pragma unroll
    for (int mt = 0; mt < 4; mt++)
#pragma unroll
        for (int nt = 0; nt < 4; nt++)
#pragma unroll
            for (int f = 0; f < 4; f++) acc[mt][nt][f] = 0.f;

    int a_row = lane & 15;                       // + wr*64 + mt*16
    int a_kb  = (lane >> 4) * 16;                // + kk*32
    int b_row = (lane & 7) + ((lane >> 4) << 3); // + wc*32 + ng*16
    int b_kb  = ((lane >> 3) & 1) * 16;          // + kk*32

#pragma unroll
    for (int kk = 0; kk < 4; kk++) {
        uint32_t af[4][4];
#pragma unroll
        for (int mt = 0; mt < 4; mt++) {
            int row = wr * 64 + mt * 16 + a_row;
            int kb = kk * 32 + a_kb;
            uint32_t addr = smem_base + SMEM_A + row * 128 + (kb ^ ((row & 7) * 16));
            ldsm_x4(af[mt], addr);
        }
        uint32_t bf[2][4];
#pragma unroll
        for (int ng = 0; ng < 2; ng++) {
            int row = wc * 32 + ng * 16 + b_row;
            int kb = kk * 32 + b_kb;
            uint32_t addr = smem_base + SMEM_B + row * 128 + (kb ^ ((row & 7) * 16));
            ldsm_x4(bf[ng], addr);
        }
#pragma unroll
        for (int mt = 0; mt < 4; mt++)
#pragma unroll
            for (int nt = 0; nt < 4; nt++)
                mma16816(acc[mt][nt], af[mt], &bf[nt >> 1][(nt & 1) * 2]);
    }

    // ---- fused epilogue: sqrt + row/col partials ----
    // acc[mt][nt]: c0=(r=lane/4, c=(lane%4)*2) c1=c+1 c2=(r+8,c) c3=(r+8,c+1)
    float rs[4][2], cs[4][2];
#pragma unroll
    for (int mt = 0; mt < 4; mt++) { rs[mt][0] = 0.f; rs[mt][1] = 0.f; }
#pragma unroll
    for (int nt = 0; nt < 4; nt++) { cs[nt][0] = 0.f; cs[nt][1] = 0.f; }
#pragma unroll
    for (int mt = 0; mt < 4; mt++)
#pragma unroll
        for (int nt = 0; nt < 4; nt++) {
            float s0 = msqrt(acc[mt][nt][0]);
            float s1 = msqrt(acc[mt][nt][1]);
            float s2 = msqrt(acc[mt][nt][2]);
            float s3 = msqrt(acc[mt][nt][3]);
            rs[mt][0] += s0 + s1;
            rs[mt][1] += s2 + s3;
            cs[nt][0] += s0 + s2;
            cs[nt][1] += s1 + s3;
        }

    // row partials: reduce across 4 lanes sharing a row (lane%4)
#pragma unroll
    for (int o = 1; o <= 2; o <<= 1)
#pragma unroll
        for (int mt = 0; mt < 4; mt++) {
            rs[mt][0] += __shfl_xor_sync(0xffffffffu, rs[mt][0], o);
            rs[mt][1] += __shfl_xor_sync(0xffffffffu, rs[mt][1], o);
        }
    // col partials: reduce across 8 lanes sharing a col (lane/4)
#pragma unroll
    for (int o = 4; o <= 16; o <<= 1)
#pragma unroll
        for (int nt = 0; nt < 4; nt++) {
            cs[nt][0] += __shfl_xor_sync(0xffffffffu, cs[nt][0], o);
            cs[nt][1] += __shfl_xor_sync(0xffffffffu, cs[nt][1], o);
        }

    __syncthreads();   // smem tile reads done; reuse as reduction buffers
    float* srow = reinterpret_cast<float*>(smem);        // [128][4] (by wc)
    float* scol = srow + 512;                            // [128][2] (by wr)

    if ((lane & 3) == 0) {
        int g = lane >> 2;  // 0..7
#pragma unroll
        for (int mt = 0; mt < 4; mt++) {
            srow[(wr * 64 + mt * 16 + g) * 4 + wc]     = rs[mt][0];
            srow[(wr * 64 + mt * 16 + g + 8) * 4 + wc] = rs[mt][1];
        }
    }
    if (lane < 4) {
#pragma unroll
        for (int nt = 0; nt < 4; nt++) {
            scol[(wc * 32 + nt * 8 + lane * 2) * 2 + wr]     = cs[nt][0];
            scol[(wc * 32 + nt * 8 + lane * 2 + 1) * 2 + wr] = cs[nt][1];
        }
    }
    __syncthreads();

    if (tid < 128) {
        const float4 v = reinterpret_cast<const float4*>(srow)[tid];
        g_part[(pair * BB + ti * 128 + tid) * NT + tj] = (v.x + v.y) + (v.z + v.w);
    } else if (ti != tj) {
        int c = tid - 128;
        g_part[(pair * BB + tj * 128 + c) * NT + ti] = scol[c * 2] + scol[c * 2 + 1];
    }
}

// ---------------------------------------------------------------------------
// Kernel 4: reduce 64 slots per row, 2 threads per row + shuffle combine
// ---------------------------------------------------------------------------
__global__ void reduce_kernel(float* __restrict__ out) {
    int idx = blockIdx.x * blockDim.x + threadIdx.x;  // 0..32767
    int row = idx >> 1, half = idx & 1;
    const float4* p = reinterpret_cast<const float4*>(&g_part[row * NT + half * 32]);
    float s = 0.f;
#pragma unroll
    for (int j = 0; j < 8; j++) {
        float4 v = p[j];
        s += (v.x + v.y) + (v.z + v.w);
    }
    s += __shfl_xor_sync(0xffffffffu, s, 1);
    if (half == 0) out[row] = s + 8192.0f * 1e-6f;
}

extern "C" void kernel_launch(void* const* d_in, const int* in_sizes, int n_in,
                              void* d_out, int out_size) {
    (void)in_sizes; (void)n_in; (void)out_size;
    const float* anchor   = (const float*)d_in[0];
    const float* positive = (const float*)d_in[1];
    const float* negative = (const float*)d_in[2];
    float* out = (float*)d_out;

    varA_kernel<<<128, 256>>>(anchor, positive, negative);
    varB_kernel<<<1, 128>>>();
    build_kernel<<<1024, 256>>>(anchor, positive, negative);
    cudaFuncSetAttribute(gemm_kernel, cudaFuncAttributeMaxDynamicSharedMemorySize, SMEM_TOTAL);
    gemm_kernel<<<dim3(NTRI, 2), 256, SMEM_TOTAL>>>();
    reduce_kernel<<<256, 128>>>(out);
}

// round 8
// speedup vs baseline: 8.2559x; 1.1404x over previous
#include <cuda_runtime.h>
#include <cuda_bf16.h>
#include <math.h>
#include <stdint.h>

#define BB 8192
#define DD 64
#define NT 64          // 128-row tiles
#define NTRI 2080      // NT*(NT+1)/2
#define NTILES (2 * NTRI)
#define GRID_GEMM 296  // 2 CTAs x 148 SMs, persistent
#define TILE_BYTES 16384
#define BUF_BYTES 32768

// ---------------- scratch (no allocations allowed) ----------------
__device__ float g_rstd[2][DD];
__device__ float g_vpart[2 * 2 * 64 * 64];   // [pair][s1|s2][chunk][d]
// Y stored PRE-SWIZZLED (SW128) per 128-row tile: tile t occupies bytes
// [t*16384, (t+1)*16384); within: off = lr*128 + col16B*16, sw-xor'd.
__device__ unsigned char g_Yb[2][BB * 128];
__device__ float g_part[2 * BB * NT];        // [pair*B + row][tile-slot]

// ---------------- helpers ----------------
__device__ __forceinline__ uint32_t smem_u32(const void* p) {
    uint32_t a;
    asm("{ .reg .u64 t; cvta.to.shared.u64 t, %1; cvt.u32.u64 %0, t; }" : "=r"(a) : "l"(p));
    return a;
}

__device__ __forceinline__ void ldsm_x4(uint32_t* r, uint32_t addr) {
    asm volatile("ldmatrix.sync.aligned.m8n8.x4.shared.b16 {%0,%1,%2,%3}, [%4];"
                 : "=r"(r[0]), "=r"(r[1]), "=r"(r[2]), "=r"(r[3]) : "r"(addr));
}

__device__ __forceinline__ void mma16816(float* d, const uint32_t* a, const uint32_t* b) {
    asm volatile(
        "mma.sync.aligned.m16n8k16.row.col.f32.bf16.bf16.f32 "
        "{%0,%1,%2,%3}, {%4,%5,%6,%7}, {%8,%9}, {%0,%1,%2,%3};"
        : "+f"(d[0]), "+f"(d[1]), "+f"(d[2]), "+f"(d[3])
        : "r"(a[0]), "r"(a[1]), "r"(a[2]), "r"(a[3]), "r"(b[0]), "r"(b[1]));
}

__device__ __forceinline__ float msqrt(float q) {
    float sv;
    asm("sqrt.approx.f32 %0, %1;" : "=f"(sv) : "f"(fmaxf(q, 0.0f)));
    return sv;
}

#define MBAR_INIT(addr, cnt) \
    asm volatile("mbarrier.init.shared.b64 [%0], %1;" :: "r"(addr), "r"(cnt) : "memory")
#define MBAR_EXPECT_TX(addr, bytes) \
    asm volatile("mbarrier.arrive.expect_tx.shared.b64 _, [%0], %1;" :: "r"(addr), "r"(bytes) : "memory")
#define MBAR_WAIT(addr, parity) do {                                              \
    uint32_t _m = (addr); uint32_t _p = (parity); uint32_t _done;                 \
    asm volatile("{ .reg .pred p;\n\t"                                            \
        "mbarrier.try_wait.parity.acquire.cta.shared::cta.b64 p, [%1], %2;\n\t"   \
        "selp.b32 %0, 1, 0, p; }" : "=r"(_done) : "r"(_m), "r"(_p) : "memory");   \
    if (!_done) {                                                                 \
        asm volatile("{ .reg .pred P1;\n\t"                                       \
        "WL_%=:\n\t"                                                              \
        "mbarrier.try_wait.parity.acquire.cta.shared::cta.b64 P1, [%0], %1, 0x989680;\n\t" \
        "@P1 bra.uni WD_%=;\n\t"                                                  \
        "bra.uni WL_%=;\n\t"                                                      \
        "WD_%=: }" :: "r"(_m), "r"(_p) : "memory");                               \
    }                                                                             \
} while (0)

__device__ __forceinline__ void bulk_copy(uint32_t dst_smem, const void* src, uint32_t bytes,
                                          uint32_t mbar) {
    asm volatile(
        "cp.async.bulk.shared::cluster.global.mbarrier::complete_tx::bytes [%0], [%1], %2, [%3];"
        :: "r"(dst_smem), "l"(src), "r"(bytes), "r"(mbar) : "memory");
}

// ---------------------------------------------------------------------------
// Kernel 1a: coalesced per-block partial sums (s1, s2) per feature.
// ---------------------------------------------------------------------------
__global__ __launch_bounds__(256) void varA_kernel(const float* __restrict__ anchor,
                                                   const float* __restrict__ positive,
                                                   const float* __restrict__ negative) {
    int pair  = blockIdx.x >> 6;
    int chunk = blockIdx.x & 63;
    const float* bp = pair ? negative : positive;
    int t = threadIdx.x;
    int g = t & 15;
    int rr = t >> 4;

    float s1[4] = {0.f, 0.f, 0.f, 0.f};
    float s2[4] = {0.f, 0.f, 0.f, 0.f};
#pragma unroll
    for (int p = 0; p < 8; p++) {
        int r = chunk * 128 + p * 16 + rr;
        float4 a = reinterpret_cast<const float4*>(anchor)[r * 16 + g];
        float4 b = reinterpret_cast<const float4*>(bp)[r * 16 + g];
        float x, y;
        x = a.x + 1e-4f; y = b.x + 1e-4f; s1[0] += x + y; s2[0] += x * x + y * y;
        x = a.y + 1e-4f; y = b.y + 1e-4f; s1[1] += x + y; s2[1] += x * x + y * y;
        x = a.z + 1e-4f; y = b.z + 1e-4f; s1[2] += x + y; s2[2] += x * x + y * y;
        x = a.w + 1e-4f; y = b.w + 1e-4f; s1[3] += x + y; s2[3] += x * x + y * y;
    }
    __shared__ float sh[256 * 8];
#pragma unroll
    for (int c = 0; c < 4; c++) {
        sh[t * 8 + c]     = s1[c];
        sh[t * 8 + 4 + c] = s2[c];
    }
    __syncthreads();
    if (t < 128) {
        int d  = t & 63;
        int wh = t >> 6;        // 0: s1, 1: s2
        int gg = d >> 2, c = d & 3;
        float s = 0.f;
#pragma unroll
        for (int k = 0; k < 16; k++)
            s += sh[(gg + 16 * k) * 8 + wh * 4 + c];
        g_vpart[((pair * 2 + wh) * 64 + chunk) * 64 + d] = s;
    }
}

// ---------------------------------------------------------------------------
// Kernel 1b: finish variance -> rstd (128 threads, one block)
// ---------------------------------------------------------------------------
__global__ void varB_kernel() {
    int t = threadIdx.x;        // 0..127
    int pair = t >> 6, d = t & 63;
    float s1 = 0.f, s2 = 0.f;
#pragma unroll 8
    for (int chunk = 0; chunk < 64; chunk++) {
        s1 += g_vpart[((pair * 2 + 0) * 64 + chunk) * 64 + d];
        s2 += g_vpart[((pair * 2 + 1) * 64 + chunk) * 64 + d];
    }
    const float n = 2.0f * BB;
    float mean = s1 / n;
    float var  = s2 / n - mean * mean;
    g_rstd[pair][d] = 1.0f / sqrtf(var);
}

// ---------------------------------------------------------------------------
// Kernel 2: Y = (a-b)*rstd (bf16), written PRE-SWIZZLED per 128-row tile so
// gemm can bulk-copy tiles linearly.
// ---------------------------------------------------------------------------
__global__ void build_kernel(const float* __restrict__ anchor,
                             const float* __restrict__ positive,
                             const float* __restrict__ negative) {
    int idx = blockIdx.x * blockDim.x + threadIdx.x;  // 0 .. 2*8192*16-1
    int pair = idx >> 17;
    int rem  = idx & 131071;
    int r = rem >> 4;
    int g = rem & 15;          // 4-feature group (8 output bytes)
    const float* bp = pair ? negative : positive;
    float4 av = reinterpret_cast<const float4*>(anchor)[r * 16 + g];
    float4 bv = reinterpret_cast<const float4*>(bp)[r * 16 + g];
    float4 rs = reinterpret_cast<const float4*>(g_rstd[pair])[g];
    __nv_bfloat162 lo = __floats2bfloat162_rn((av.x - bv.x) * rs.x, (av.y - bv.y) * rs.y);
    __nv_bfloat162 hi = __floats2bfloat162_rn((av.z - bv.z) * rs.z, (av.w - bv.w) * rs.w);
    uint2 pk;
    *reinterpret_cast<__nv_bfloat162*>(&pk.x) = lo;
    *reinterpret_cast<__nv_bfloat162*>(&pk.y) = hi;
    int tile = r >> 7, lr = r & 127;
    uint32_t off = (uint32_t)lr * 128 + g * 8;
    uint32_t sw = off ^ ((off >> 3) & 0x70);
    *reinterpret_cast<uint2*>(&g_Yb[pair][tile * TILE_BYTES + sw]) = pk;
}

// ---------------------------------------------------------------------------
// Kernel 3: persistent triangular GEMM, 2-stage cp.async.bulk pipeline.
// 256 threads, 8 warps, warp tile 64x32. Fused sqrt + row/col partials.
// ---------------------------------------------------------------------------
__global__ __launch_bounds__(256, 2) void gemm_kernel() {
    extern __shared__ char smem[];                 // 2 x 32KB tile buffers
    __shared__ float srow2[2][512];
    __shared__ float scol2[2][256];
    __shared__ __align__(8) uint64_t mbar_full[2];

    uint32_t smem_base = smem_u32(smem);
    uint32_t mbar0 = smem_u32(&mbar_full[0]);
    int tid = threadIdx.x;
    int lane = tid & 31;
    int wid = tid >> 5;
    int wr = wid >> 2;    // warp row (0,1) -> rows wr*64
    int wc = wid & 3;     // warp col (0..3) -> cols wc*32

    if (tid == 0) {
        MBAR_INIT(mbar0, 1);
        MBAR_INIT(mbar0 + 8, 1);
    }
    __syncthreads();

    // Prologue: issue tiles n=0,1 into buffers 0,1.
    if (tid == 0) {
#pragma unroll
        for (int s = 0; s < 2; s++) {
            int idx = blockIdx.x + s * GRID_GEMM;
            if (idx < NTILES) {
                int pair = idx >= NTRI;
                int tt = idx - pair * NTRI;
                int tj = (int)((sqrtf(8.0f * (float)tt + 1.0f) - 1.0f) * 0.5f);
                while ((tj + 1) * (tj + 2) / 2 <= tt) tj++;
                while (tj * (tj + 1) / 2 > tt) tj--;
                int ti = tt - tj * (tj + 1) / 2;
                uint32_t dst = smem_base + s * BUF_BYTES;
                MBAR_EXPECT_TX(mbar0 + 8 * s, BUF_BYTES);
                bulk_copy(dst, g_Yb[pair] + ti * TILE_BYTES, TILE_BYTES, mbar0 + 8 * s);
                bulk_copy(dst + TILE_BYTES, g_Yb[pair] + tj * TILE_BYTES, TILE_BYTES, mbar0 + 8 * s);
            }
        }
    }

    int a_row = lane & 15;                       // + wr*64 + mt*16
    int a_kb  = (lane >> 4) * 16;                // + kk*32
    int b_row = (lane & 7) + ((lane >> 4) << 3); // + wc*32 + ng*16
    int b_kb  = ((lane >> 3) & 1) * 16;          // + kk*32

    int n = 0;
    for (int idx = blockIdx.x; idx < NTILES; idx += GRID_GEMM, n++) {
        int buf = n & 1;
        uint32_t base = smem_base + buf * BUF_BYTES;

        int pair = idx >= NTRI;
        int tt = idx - pair * NTRI;
        int tj = (int)((sqrtf(8.0f * (float)tt + 1.0f) - 1.0f) * 0.5f);
        while ((tj + 1) * (tj + 2) / 2 <= tt) tj++;
        while (tj * (tj + 1) / 2 > tt) tj--;
        int ti = tt - tj * (tj + 1) / 2;

        MBAR_WAIT(mbar0 + 8 * buf, (n >> 1) & 1);

        // ---- mainloop: 4 k16 steps, warp tile 64x32 ----
        float acc[4][4][4];
#pragma unroll
        for (int mt = 0; mt < 4; mt++)
#pragma unroll
            for (int nt = 0; nt < 4; nt++)
#pragma unroll
                for (int f = 0; f < 4; f++) acc[mt][nt][f] = 0.f;

#pragma unroll
        for (int kk = 0; kk < 4; kk++) {
            uint32_t af[4][4];
#pragma unroll
            for (int mt = 0; mt < 4; mt++) {
                int row = wr * 64 + mt * 16 + a_row;
                int kb = kk * 32 + a_kb;
                uint32_t addr = base + row * 128 + (kb ^ ((row & 7) * 16));
                ldsm_x4(af[mt], addr);
            }
            uint32_t bfr[2][4];
#pragma unroll
            for (int ng = 0; ng < 2; ng++) {
                int row = wc * 32 + ng * 16 + b_row;
                int kb = kk * 32 + b_kb;
                uint32_t addr = base + TILE_BYTES + row * 128 + (kb ^ ((row & 7) * 16));
                ldsm_x4(bfr[ng], addr);
            }
#pragma unroll
            for (int mt = 0; mt < 4; mt++)
#pragma unroll
                for (int nt = 0; nt < 4; nt++)
                    mma16816(acc[mt][nt], af[mt], &bfr[nt >> 1][(nt & 1) * 2]);
        }

        // ---- fused epilogue: sqrt + row/col partials ----
        float rs[4][2], cs[4][2];
#pragma unroll
        for (int mt = 0; mt < 4; mt++) { rs[mt][0] = 0.f; rs[mt][1] = 0.f; }
#pragma unroll
        for (int nt = 0; nt < 4; nt++) { cs[nt][0] = 0.f; cs[nt][1] = 0.f; }
#pragma unroll
        for (int mt = 0; mt < 4; mt++)
#pragma unroll
            for (int nt = 0; nt < 4; nt++) {
                float s0 = msqrt(acc[mt][nt][0]);
                float s1 = msqrt(acc[mt][nt][1]);
                float s2 = msqrt(acc[mt][nt][2]);
                float s3 = msqrt(acc[mt][nt][3]);
                rs[mt][0] += s0 + s1;
                rs[mt][1] += s2 + s3;
                cs[nt][0] += s0 + s2;
                cs[nt][1] += s1 + s3;
            }

#pragma unroll
        for (int o = 1; o <= 2; o <<= 1)
#pragma unroll
            for (int mt = 0; mt < 4; mt++) {
                rs[mt][0] += __shfl_xor_sync(0xffffffffu, rs[mt][0], o);
                rs[mt][1] += __shfl_xor_sync(0xffffffffu, rs[mt][1], o);
            }
#pragma unroll
        for (int o = 4; o <= 16; o <<= 1)
#pragma unroll
            for (int nt = 0; nt < 4; nt++) {
                cs[nt][0] += __shfl_xor_sync(0xffffffffu, cs[nt][0], o);
                cs[nt][1] += __shfl_xor_sync(0xffffffffu, cs[nt][1], o);
            }

        float* srow = srow2[buf];
        float* scol = scol2[buf];
        if ((lane & 3) == 0) {
            int g = lane >> 2;  // 0..7
#pragma unroll
            for (int mt = 0; mt < 4; mt++) {
                srow[(wr * 64 + mt * 16 + g) * 4 + wc]     = rs[mt][0];
                srow[(wr * 64 + mt * 16 + g + 8) * 4 + wc] = rs[mt][1];
            }
        }
        if (lane < 4) {
#pragma unroll
            for (int nt = 0; nt < 4; nt++) {
                scol[(wc * 32 + nt * 8 + lane * 2) * 2 + wr]     = cs[nt][0];
                scol[(wc * 32 + nt * 8 + lane * 2 + 1) * 2 + wr] = cs[nt][1];
            }
        }
        __syncthreads();   // all mainloop reads of `buf` complete past this point

        // Producer: refill this buffer with tile n+2.
        if (tid == 0) {
            int idx2 = idx + 2 * GRID_GEMM;
            if (idx2 < NTILES) {
                int pair2 = idx2 >= NTRI;
                int t2 = idx2 - pair2 * NTRI;
                int tj2 = (int)((sqrtf(8.0f * (float)t2 + 1.0f) - 1.0f) * 0.5f);
                while ((tj2 + 1) * (tj2 + 2) / 2 <= t2) tj2++;
                while (tj2 * (tj2 + 1) / 2 > t2) tj2--;
                int ti2 = t2 - tj2 * (tj2 + 1) / 2;
                uint32_t dst = smem_base + buf * BUF_BYTES;
                MBAR_EXPECT_TX(mbar0 + 8 * buf, BUF_BYTES);
                bulk_copy(dst, g_Yb[pair2] + ti2 * TILE_BYTES, TILE_BYTES, mbar0 + 8 * buf);
                bulk_copy(dst + TILE_BYTES, g_Yb[pair2] + tj2 * TILE_BYTES, TILE_BYTES, mbar0 + 8 * buf);
            }
        }

        if (tid < 128) {
            const float4 v = reinterpret_cast<const float4*>(srow)[tid];
            g_part[(pair * BB + ti * 128 + tid) * NT + tj] = (v.x + v.y) + (v.z + v.w);
        } else if (ti != tj) {
            int c = tid - 128;
            g_part[(pair * BB + tj * 128 + c) * NT + ti] = scol[c * 2] + scol[c * 2 + 1];
        }
    }
}

// ---------------------------------------------------------------------------
// Kernel 4: reduce 64 slots per row, 2 threads per row + shuffle combine
// ---------------------------------------------------------------------------
__global__ void reduce_kernel(float* __restrict__ out) {
    int idx = blockIdx.x * blockDim.x + threadIdx.x;  // 0..32767
    int row = idx >> 1, half = idx & 1;
    const float4* p = reinterpret_cast<const float4*>(&g_part[row * NT + half * 32]);
    float s = 0.f;
#pragma unroll
    for (int j = 0; j < 8; j++) {
        float4 v = p[j];
        s += (v.x + v.y) + (v.z + v.w);
    }
    s += __shfl_xor_sync(0xffffffffu, s, 1);
    if (half == 0) out[row] = s + 8192.0f * 1e-6f;
}

extern "C" void kernel_launch(void* const* d_in, const int* in_sizes, int n_in,
                              void* d_out, int out_size) {
    (void)in_sizes; (void)n_in; (void)out_size;
    const float* anchor   = (const float*)d_in[0];
    const float* positive = (const float*)d_in[1];
    const float* negative = (const float*)d_in[2];
    float* out = (float*)d_out;

    varA_kernel<<<128, 256>>>(anchor, positive, negative);
    varB_kernel<<<1, 128>>>();
    build_kernel<<<1024, 256>>>(anchor, positive, negative);
    cudaFuncSetAttribute(gemm_kernel, cudaFuncAttributeMaxDynamicSharedMemorySize, 2 * BUF_BYTES);
    gemm_kernel<<<GRID_GEMM, 256, 2 * BUF_BYTES>>>();
    reduce_kernel<<<256, 128>>>(out);
}

// round 9
// speedup vs baseline: 8.3203x; 1.0078x over previous
#include <cuda_runtime.h>
#include <cuda_bf16.h>
#include <math.h>
#include <stdint.h>

#define BB 8192
#define DD 64
#define NT 64          // 128-row tiles
#define NTRI 2080      // NT*(NT+1)/2
#define NTILES (2 * NTRI)
#define GRID_GEMM 296  // 2 CTAs x 148 SMs, persistent
#define TILE_BYTES 16384
#define BUF_BYTES 32768
#define NSTAGE 3

// ---------------- scratch (no allocations allowed) ----------------
__device__ float g_rstd[2][DD];
__device__ float g_vpart[2 * 2 * 64 * 64];   // [pair][s1|s2][chunk][d]
// Y stored PRE-SWIZZLED (SW128) per 128-row tile.
__device__ unsigned char g_Yb[2][BB * 128];
// TRANSPOSED partials: [slot][pair*BB + row] -> coalesced STG and LDG.
__device__ float g_part[NT][2 * BB];

// ---------------- helpers ----------------
__device__ __forceinline__ uint32_t smem_u32(const void* p) {
    uint32_t a;
    asm("{ .reg .u64 t; cvta.to.shared.u64 t, %1; cvt.u32.u64 %0, t; }" : "=r"(a) : "l"(p));
    return a;
}

__device__ __forceinline__ void ldsm_x4(uint32_t* r, uint32_t addr) {
    asm volatile("ldmatrix.sync.aligned.m8n8.x4.shared.b16 {%0,%1,%2,%3}, [%4];"
                 : "=r"(r[0]), "=r"(r[1]), "=r"(r[2]), "=r"(r[3]) : "r"(addr));
}

__device__ __forceinline__ void mma16816(float* d, const uint32_t* a, const uint32_t* b) {
    asm volatile(
        "mma.sync.aligned.m16n8k16.row.col.f32.bf16.bf16.f32 "
        "{%0,%1,%2,%3}, {%4,%5,%6,%7}, {%8,%9}, {%0,%1,%2,%3};"
        : "+f"(d[0]), "+f"(d[1]), "+f"(d[2]), "+f"(d[3])
        : "r"(a[0]), "r"(a[1]), "r"(a[2]), "r"(a[3]), "r"(b[0]), "r"(b[1]));
}

__device__ __forceinline__ float msqrt(float q) {
    float sv;
    asm("sqrt.approx.f32 %0, %1;" : "=f"(sv) : "f"(fmaxf(q, 0.0f)));
    return sv;
}

#define MBAR_INIT(addr, cnt) \
    asm volatile("mbarrier.init.shared.b64 [%0], %1;" :: "r"(addr), "r"(cnt) : "memory")
#define MBAR_EXPECT_TX(addr, bytes) \
    asm volatile("mbarrier.arrive.expect_tx.shared.b64 _, [%0], %1;" :: "r"(addr), "r"(bytes) : "memory")
#define MBAR_WAIT(addr, parity) do {                                              \
    uint32_t _m = (addr); uint32_t _p = (parity); uint32_t _done;                 \
    asm volatile("{ .reg .pred p;\n\t"                                            \
        "mbarrier.try_wait.parity.acquire.cta.shared::cta.b64 p, [%1], %2;\n\t"   \
        "selp.b32 %0, 1, 0, p; }" : "=r"(_done) : "r"(_m), "r"(_p) : "memory");   \
    if (!_done) {                                                                 \
        asm volatile("{ .reg .pred P1;\n\t"                                       \
        "WL_%=:\n\t"                                                              \
        "mbarrier.try_wait.parity.acquire.cta.shared::cta.b64 P1, [%0], %1, 0x989680;\n\t" \
        "@P1 bra.uni WD_%=;\n\t"                                                  \
        "bra.uni WL_%=;\n\t"                                                      \
        "WD_%=: }" :: "r"(_m), "r"(_p) : "memory");                               \
    }                                                                             \
} while (0)

__device__ __forceinline__ void bulk_copy(uint32_t dst_smem, const void* src, uint32_t bytes,
                                          uint32_t mbar) {
    asm volatile(
        "cp.async.bulk.shared::cluster.global.mbarrier::complete_tx::bytes [%0], [%1], %2, [%3];"
        :: "r"(dst_smem), "l"(src), "r"(bytes), "r"(mbar) : "memory");
}

__device__ __forceinline__ void tri_decode(int tt, int& ti, int& tj) {
    int j = (int)((sqrtf(8.0f * (float)tt + 1.0f) - 1.0f) * 0.5f);
    while ((j + 1) * (j + 2) / 2 <= tt) j++;
    while (j * (j + 1) / 2 > tt) j--;
    tj = j;
    ti = tt - j * (j + 1) / 2;
}

// ---------------------------------------------------------------------------
// Kernel 1a: coalesced per-block partial sums (s1, s2) per feature.
// ---------------------------------------------------------------------------
__global__ __launch_bounds__(256) void varA_kernel(const float* __restrict__ anchor,
                                                   const float* __restrict__ positive,
                                                   const float* __restrict__ negative) {
    int pair  = blockIdx.x >> 6;
    int chunk = blockIdx.x & 63;
    const float* bp = pair ? negative : positive;
    int t = threadIdx.x;
    int g = t & 15;
    int rr = t >> 4;

    float s1[4] = {0.f, 0.f, 0.f, 0.f};
    float s2[4] = {0.f, 0.f, 0.f, 0.f};
#pragma unroll
    for (int p = 0; p < 8; p++) {
        int r = chunk * 128 + p * 16 + rr;
        float4 a = reinterpret_cast<const float4*>(anchor)[r * 16 + g];
        float4 b = reinterpret_cast<const float4*>(bp)[r * 16 + g];
        float x, y;
        x = a.x + 1e-4f; y = b.x + 1e-4f; s1[0] += x + y; s2[0] += x * x + y * y;
        x = a.y + 1e-4f; y = b.y + 1e-4f; s1[1] += x + y; s2[1] += x * x + y * y;
        x = a.z + 1e-4f; y = b.z + 1e-4f; s1[2] += x + y; s2[2] += x * x + y * y;
        x = a.w + 1e-4f; y = b.w + 1e-4f; s1[3] += x + y; s2[3] += x * x + y * y;
    }
    __shared__ float sh[256 * 8];
#pragma unroll
    for (int c = 0; c < 4; c++) {
        sh[t * 8 + c]     = s1[c];
        sh[t * 8 + 4 + c] = s2[c];
    }
    __syncthreads();
    if (t < 128) {
        int d  = t & 63;
        int wh = t >> 6;        // 0: s1, 1: s2
        int gg = d >> 2, c = d & 3;
        float s = 0.f;
#pragma unroll
        for (int k = 0; k < 16; k++)
            s += sh[(gg + 16 * k) * 8 + wh * 4 + c];
        g_vpart[((pair * 2 + wh) * 64 + chunk) * 64 + d] = s;
    }
}

// ---------------------------------------------------------------------------
// Kernel 1b: finish variance -> rstd (128 threads, one block)
// ---------------------------------------------------------------------------
__global__ void varB_kernel() {
    int t = threadIdx.x;        // 0..127
    int pair = t >> 6, d = t & 63;
    float s1 = 0.f, s2 = 0.f;
#pragma unroll 8
    for (int chunk = 0; chunk < 64; chunk++) {
        s1 += g_vpart[((pair * 2 + 0) * 64 + chunk) * 64 + d];
        s2 += g_vpart[((pair * 2 + 1) * 64 + chunk) * 64 + d];
    }
    const float n = 2.0f * BB;
    float mean = s1 / n;
    float var  = s2 / n - mean * mean;
    g_rstd[pair][d] = 1.0f / sqrtf(var);
}

// ---------------------------------------------------------------------------
// Kernel 2: Y = (a-b)*rstd (bf16), written PRE-SWIZZLED per 128-row tile.
// ---------------------------------------------------------------------------
__global__ void build_kernel(const float* __restrict__ anchor,
                             const float* __restrict__ positive,
                             const float* __restrict__ negative) {
    int idx = blockIdx.x * blockDim.x + threadIdx.x;  // 0 .. 2*8192*16-1
    int pair = idx >> 17;
    int rem  = idx & 131071;
    int r = rem >> 4;
    int g = rem & 15;          // 4-feature group (8 output bytes)
    const float* bp = pair ? negative : positive;
    float4 av = reinterpret_cast<const float4*>(anchor)[r * 16 + g];
    float4 bv = reinterpret_cast<const float4*>(bp)[r * 16 + g];
    float4 rs = reinterpret_cast<const float4*>(g_rstd[pair])[g];
    __nv_bfloat162 lo = __floats2bfloat162_rn((av.x - bv.x) * rs.x, (av.y - bv.y) * rs.y);
    __nv_bfloat162 hi = __floats2bfloat162_rn((av.z - bv.z) * rs.z, (av.w - bv.w) * rs.w);
    uint2 pk;
    *reinterpret_cast<__nv_bfloat162*>(&pk.x) = lo;
    *reinterpret_cast<__nv_bfloat162*>(&pk.y) = hi;
    int tile = r >> 7, lr = r & 127;
    uint32_t off = (uint32_t)lr * 128 + g * 8;
    uint32_t sw = off ^ ((off >> 3) & 0x70);
    *reinterpret_cast<uint2*>(&g_Yb[pair][tile * TILE_BYTES + sw]) = pk;
}

// ---------------------------------------------------------------------------
// Kernel 3: persistent triangular GEMM, 3-stage cp.async.bulk pipeline.
// 256 threads, 8 warps, warp tile 64x32. Fused sqrt + row/col partials.
// ---------------------------------------------------------------------------
__global__ __launch_bounds__(256, 2) void gemm_kernel() {
    extern __shared__ char smem[];                 // NSTAGE x 32KB tile buffers
    __shared__ float srow2[2][512];
    __shared__ float scol2[2][256];
    __shared__ __align__(8) uint64_t mbar_full[NSTAGE];

    uint32_t smem_base = smem_u32(smem);
    uint32_t mbar0 = smem_u32(&mbar_full[0]);
    int tid = threadIdx.x;
    int lane = tid & 31;
    int wid = tid >> 5;
    int wr = wid >> 2;    // warp row (0,1) -> rows wr*64
    int wc = wid & 3;     // warp col (0..3) -> cols wc*32

    if (tid == 0) {
#pragma unroll
        for (int s = 0; s < NSTAGE; s++) MBAR_INIT(mbar0 + 8 * s, 1);
    }
    __syncthreads();

    // Prologue: issue tiles n=0..NSTAGE-1 into their buffers.
    if (tid == 0) {
#pragma unroll
        for (int s = 0; s < NSTAGE; s++) {
            int idx = blockIdx.x + s * GRID_GEMM;
            if (idx < NTILES) {
                int pair = idx >= NTRI;
                int ti, tj;
                tri_decode(idx - pair * NTRI, ti, tj);
                uint32_t dst = smem_base + s * BUF_BYTES;
                MBAR_EXPECT_TX(mbar0 + 8 * s, BUF_BYTES);
                bulk_copy(dst, g_Yb[pair] + ti * TILE_BYTES, TILE_BYTES, mbar0 + 8 * s);
                bulk_copy(dst + TILE_BYTES, g_Yb[pair] + tj * TILE_BYTES, TILE_BYTES, mbar0 + 8 * s);
            }
        }
    }

    int a_row = lane & 15;                       // + wr*64 + mt*16
    int a_kb  = (lane >> 4) * 16;                // + kk*32
    int b_row = (lane & 7) + ((lane >> 4) << 3); // + wc*32 + ng*16
    int b_kb  = ((lane >> 3) & 1) * 16;          // + kk*32

    int n = 0;
    int buf = 0;
    for (int idx = blockIdx.x; idx < NTILES; idx += GRID_GEMM, n++) {
        uint32_t base = smem_base + buf * BUF_BYTES;

        int pair = idx >= NTRI;
        int ti, tj;
        tri_decode(idx - pair * NTRI, ti, tj);

        MBAR_WAIT(mbar0 + 8 * buf, (n / NSTAGE) & 1);

        // ---- mainloop: 4 k16 steps, warp tile 64x32 ----
        float acc[4][4][4];
#pragma unroll
        for (int mt = 0; mt < 4; mt++)
#pragma unroll
            for (int nt = 0; nt < 4; nt++)
#pragma unroll
                for (int f = 0; f < 4; f++) acc[mt][nt][f] = 0.f;

#pragma unroll
        for (int kk = 0; kk < 4; kk++) {
            uint32_t af[4][4];
#pragma unroll
            for (int mt = 0; mt < 4; mt++) {
                int row = wr * 64 + mt * 16 + a_row;
                int kb = kk * 32 + a_kb;
                uint32_t addr = base + row * 128 + (kb ^ ((row & 7) * 16));
                ldsm_x4(af[mt], addr);
            }
            uint32_t bfr[2][4];
#pragma unroll
            for (int ng = 0; ng < 2; ng++) {
                int row = wc * 32 + ng * 16 + b_row;
                int kb = kk * 32 + b_kb;
                uint32_t addr = base + TILE_BYTES + row * 128 + (kb ^ ((row & 7) * 16));
                ldsm_x4(bfr[ng], addr);
            }
#pragma unroll
            for (int mt = 0; mt < 4; mt++)
#pragma unroll
                for (int nt = 0; nt < 4; nt++)
                    mma16816(acc[mt][nt], af[mt], &bfr[nt >> 1][(nt & 1) * 2]);
        }

        // ---- fused epilogue: sqrt + row/col partials ----
        float rs[4][2], cs[4][2];
#pragma unroll
        for (int mt = 0; mt < 4; mt++) { rs[mt][0] = 0.f; rs[mt][1] = 0.f; }
#pragma unroll
        for (int nt = 0; nt < 4; nt++) { cs[nt][0] = 0.f; cs[nt][1] = 0.f; }
#pragma unroll
        for (int mt = 0; mt < 4; mt++)
#pragma unroll
            for (int nt = 0; nt < 4; nt++) {
                float s0 = msqrt(acc[mt][nt][0]);
                float s1 = msqrt(acc[mt][nt][1]);
                float s2 = msqrt(acc[mt][nt][2]);
                float s3 = msqrt(acc[mt][nt][3]);
                rs[mt][0] += s0 + s1;
                rs[mt][1] += s2 + s3;
                cs[nt][0] += s0 + s2;
                cs[nt][1] += s1 + s3;
            }

#pragma unroll
        for (int o = 1; o <= 2; o <<= 1)
#pragma unroll
            for (int mt = 0; mt < 4; mt++) {
                rs[mt][0] += __shfl_xor_sync(0xffffffffu, rs[mt][0], o);
                rs[mt][1] += __shfl_xor_sync(0xffffffffu, rs[mt][1], o);
            }
#pragma unroll
        for (int o = 4; o <= 16; o <<= 1)
#pragma unroll
            for (int nt = 0; nt < 4; nt++) {
                cs[nt][0] += __shfl_xor_sync(0xffffffffu, cs[nt][0], o);
                cs[nt][1] += __shfl_xor_sync(0xffffffffu, cs[nt][1], o);
            }

        float* srow = srow2[n & 1];
        float* scol = scol2[n & 1];
        if ((lane & 3) == 0) {
            int g = lane >> 2;  // 0..7
#pragma unroll
            for (int mt = 0; mt < 4; mt++) {
                srow[(wr * 64 + mt * 16 + g) * 4 + wc]     = rs[mt][0];
                srow[(wr * 64 + mt * 16 + g + 8) * 4 + wc] = rs[mt][1];
            }
        }
        if (lane < 4) {
#pragma unroll
            for (int nt = 0; nt < 4; nt++) {
                scol[(wc * 32 + nt * 8 + lane * 2) * 2 + wr]     = cs[nt][0];
                scol[(wc * 32 + nt * 8 + lane * 2 + 1) * 2 + wr] = cs[nt][1];
            }
        }
        __syncthreads();   // all mainloop reads of `buf` complete past this point

        // Producer: refill this buffer with tile n+NSTAGE.
        if (tid == 0) {
            int idx2 = idx + NSTAGE * GRID_GEMM;
            if (idx2 < NTILES) {
                int pair2 = idx2 >= NTRI;
                int ti2, tj2;
                tri_decode(idx2 - pair2 * NTRI, ti2, tj2);
                uint32_t dst = smem_base + buf * BUF_BYTES;
                MBAR_EXPECT_TX(mbar0 + 8 * buf, BUF_BYTES);
                bulk_copy(dst, g_Yb[pair2] + ti2 * TILE_BYTES, TILE_BYTES, mbar0 + 8 * buf);
                bulk_copy(dst + TILE_BYTES, g_Yb[pair2] + tj2 * TILE_BYTES, TILE_BYTES, mbar0 + 8 * buf);
            }
        }

        // Coalesced partial writes: g_part[slot][pair*BB + row]
        if (tid < 128) {
            const float4 v = reinterpret_cast<const float4*>(srow)[tid];
            g_part[tj][pair * BB + ti * 128 + tid] = (v.x + v.y) + (v.z + v.w);
        } else if (ti != tj) {
            int c = tid - 128;
            g_part[ti][pair * BB + tj * 128 + c] = scol[c * 2] + scol[c * 2 + 1];
        }

        buf++;
        if (buf == NSTAGE) buf = 0;
    }
}

// ---------------------------------------------------------------------------
// Kernel 4: reduce 64 slots per row (coalesced: consecutive threads read
// consecutive rows within each slot), 4-way ILP.
// ---------------------------------------------------------------------------
__global__ __launch_bounds__(256) void reduce_kernel(float* __restrict__ out) {
    int row = blockIdx.x * blockDim.x + threadIdx.x;  // 0..16383
    float s0 = 0.f, s1 = 0.f, s2 = 0.f, s3 = 0.f;
#pragma unroll
    for (int j = 0; j < NT; j += 4) {
        s0 += g_part[j + 0][row];
        s1 += g_part[j + 1][row];
        s2 += g_part[j + 2][row];
        s3 += g_part[j + 3][row];
    }
    out[row] = (s0 + s1) + (s2 + s3) + 8192.0f * 1e-6f;
}

extern "C" void kernel_launch(void* const* d_in, const int* in_sizes, int n_in,
                              void* d_out, int out_size) {
    (void)in_sizes; (void)n_in; (void)out_size;
    const float* anchor   = (const float*)d_in[0];
    const float* positive = (const float*)d_in[1];
    const float* negative = (const float*)d_in[2];
    float* out = (float*)d_out;

    varA_kernel<<<128, 256>>>(anchor, positive, negative);
    varB_kernel<<<1, 128>>>();
    build_kernel<<<1024, 256>>>(anchor, positive, negative);
    cudaFuncSetAttribute(gemm_kernel, cudaFuncAttributeMaxDynamicSharedMemorySize,
                         NSTAGE * BUF_BYTES);
    gemm_kernel<<<GRID_GEMM, 256, NSTAGE * BUF_BYTES>>>();
    reduce_kernel<<<64, 256>>>(out);
}